// round 1
// baseline (speedup 1.0000x reference)
#include <cuda_runtime.h>
#include <math.h>

// AFM layer: B=2048, F=50 fields, E=64, A=10, P=1225 pairs.
// out[b] = sum_p softmax(l)_p * q_p
//   l_p = sum_f h_f * relu( sum_e x_i,e * x_j,e * W_e,f + b_f )
//   q_p = sum_e x_i,e * x_j,e * p_e
// One block per batch element; 256 threads; 5 pairs/thread.

#define NF 50
#define NE 64
#define NA 10
#define NPAIR 1225          // NF*(NF-1)/2
#define THREADS 256
#define PPT 5               // max pairs per thread (ceil(1225/256))
#define XPITCH 65           // padded row (65 mod 32 -> conflict-free strided j loads)

__global__ __launch_bounds__(THREADS, 2)
void afm_kernel(const float* __restrict__ x,
                const float* __restrict__ W,
                const float* __restrict__ bvec,
                const float* __restrict__ hvec,
                const float* __restrict__ pvec,
                float* __restrict__ out)
{
    __shared__ float xs[NF * XPITCH];       // 13000 B
    __shared__ float Ws[NE * NA];           // 2560 B
    __shared__ float ps[NE];
    __shared__ float bs[NA];
    __shared__ float hs[NA];
    __shared__ unsigned char pairI[NPAIR];
    __shared__ unsigned char pairJ[NPAIR];
    __shared__ float red[32];
    __shared__ float red2[32];
    __shared__ float bcast;

    const int tid  = threadIdx.x;
    const int lane = tid & 31;
    const int wid  = tid >> 5;
    const int b    = blockIdx.x;

    // ---- load x[b] tile into padded smem (coalesced gmem reads) ----
    const float* xb = x + (size_t)b * (NF * NE);
    for (int idx = tid; idx < NF * NE; idx += THREADS) {
        int r = idx >> 6;          // /64
        int c = idx & 63;
        xs[r * XPITCH + c] = xb[idx];
    }
    for (int idx = tid; idx < NE * NA; idx += THREADS) Ws[idx] = W[idx];
    for (int idx = tid; idx < NE; idx += THREADS)      ps[idx] = pvec[idx];
    if (tid < NA) { bs[tid] = bvec[tid]; hs[tid] = hvec[tid]; }

    // ---- pair (i,j) LUT: triu_indices(F, k=1), i-major ----
    // S(i) = i*(2F-1-i)/2 pairs precede row i
    for (int p = tid; p < NPAIR; p += THREADS) {
        float fp = (float)p;
        int i = (int)((2.0f * NF - 1.0f -
                       sqrtf((2.0f * NF - 1.0f) * (2.0f * NF - 1.0f) - 8.0f * fp)) * 0.5f);
        if (i < 0) i = 0;
        if (i > NF - 2) i = NF - 2;
        while (i + 1 <= NF - 2 && (i + 1) * (2 * NF - 1 - (i + 1)) / 2 <= p) ++i;
        while (i > 0 && i * (2 * NF - 1 - i) / 2 > p) --i;
        int j = p - i * (2 * NF - 1 - i) / 2 + i + 1;
        pairI[p] = (unsigned char)i;
        pairJ[p] = (unsigned char)j;
    }
    __syncthreads();

    // ---- assign this thread's pairs ----
    int xioff[PPT], xjoff[PPT];
    bool valid[PPT];
#pragma unroll
    for (int k = 0; k < PPT; ++k) {
        int p = tid + k * THREADS;
        if (p < NPAIR) {
            xioff[k] = (int)pairI[p] * XPITCH;
            xjoff[k] = (int)pairJ[p] * XPITCH;
            valid[k] = true;
        } else {
            xioff[k] = 0;
            xjoff[k] = XPITCH;
            valid[k] = false;
        }
    }

    // ---- phase 1: per-pair attention accumulators + q scalar ----
    float acc[PPT][NA];
    float accq[PPT];
#pragma unroll
    for (int t = 0; t < PPT; ++t) {
        accq[t] = 0.0f;
#pragma unroll
        for (int f = 0; f < NA; ++f) acc[t][f] = 0.0f;
    }

#pragma unroll 1
    for (int ec = 0; ec < NE; ec += 2) {
        // hoist weights for this e-chunk into registers (uniform -> LDS broadcast)
        float w0[NA], w1[NA];
        float pp0 = ps[ec];
        float pp1 = ps[ec + 1];
#pragma unroll
        for (int f = 0; f < NA; ++f) {
            w0[f] = Ws[ec * NA + f];
            w1[f] = Ws[ec * NA + NA + f];
        }
#pragma unroll
        for (int t = 0; t < PPT; ++t) {
            const float* xi = xs + xioff[t] + ec;
            const float* xj = xs + xjoff[t] + ec;
            float pr0 = xi[0] * xj[0];
            float pr1 = xi[1] * xj[1];
            accq[t] = fmaf(pr0, pp0, accq[t]);
            accq[t] = fmaf(pr1, pp1, accq[t]);
#pragma unroll
            for (int f = 0; f < NA; ++f) {
                acc[t][f] = fmaf(pr0, w0[f], acc[t][f]);
                acc[t][f] = fmaf(pr1, w1[f], acc[t][f]);
            }
        }
    }

    // ---- logits ----
    float logit[PPT];
#pragma unroll
    for (int t = 0; t < PPT; ++t) {
        float l = 0.0f;
#pragma unroll
        for (int f = 0; f < NA; ++f) {
            float a = acc[t][f] + bs[f];
            a = a > 0.0f ? a : 0.0f;
            l = fmaf(hs[f], a, l);
        }
        logit[t] = valid[t] ? l : -INFINITY;
    }

    // ---- phase 2: softmax-weighted scalar reduction ----
    // block max
    float m = logit[0];
#pragma unroll
    for (int t = 1; t < PPT; ++t) m = fmaxf(m, logit[t]);
#pragma unroll
    for (int o = 16; o > 0; o >>= 1)
        m = fmaxf(m, __shfl_xor_sync(0xFFFFFFFFu, m, o));
    if (lane == 0) red[wid] = m;
    __syncthreads();
    if (tid == 0) {
        float mm = red[0];
#pragma unroll
        for (int w = 1; w < THREADS / 32; ++w) mm = fmaxf(mm, red[w]);
        bcast = mm;
    }
    __syncthreads();
    const float mAll = bcast;

    // exp-sum and exp*q-sum
    float s = 0.0f, sq = 0.0f;
#pragma unroll
    for (int t = 0; t < PPT; ++t) {
        if (valid[t]) {
            float e = expf(logit[t] - mAll);
            s += e;
            sq = fmaf(e, accq[t], sq);
        }
    }
#pragma unroll
    for (int o = 16; o > 0; o >>= 1) {
        s  += __shfl_xor_sync(0xFFFFFFFFu, s, o);
        sq += __shfl_xor_sync(0xFFFFFFFFu, sq, o);
    }
    if (lane == 0) { red[wid] = s; red2[wid] = sq; }
    __syncthreads();
    if (tid == 0) {
        float ss = 0.0f, ssq = 0.0f;
#pragma unroll
        for (int w = 0; w < THREADS / 32; ++w) { ss += red[w]; ssq += red2[w]; }
        out[b] = ssq / ss;
    }
}

extern "C" void kernel_launch(void* const* d_in, const int* in_sizes, int n_in,
                              void* d_out, int out_size)
{
    const float* x = (const float*)d_in[0];   // [B, 50, 64]
    const float* W = (const float*)d_in[1];   // [64, 10]
    const float* b = (const float*)d_in[2];   // [10]
    const float* h = (const float*)d_in[3];   // [10, 1]
    const float* p = (const float*)d_in[4];   // [64, 1]
    float* out = (float*)d_out;               // [B, 1]

    int B = in_sizes[0] / (NF * NE);
    afm_kernel<<<B, THREADS>>>(x, W, b, h, p, out);
}

// round 2
// speedup vs baseline: 1.1186x; 1.1186x over previous
#include <cuda_runtime.h>
#include <math.h>

// AFM layer: B=2048, F=50, E=64, A=10, P=1225.
// out[b] = sum_p softmax(l)_p * q_p
//   l_p = sum_f h_f * relu( (x_i ∘ x_j)·W_f + b_f ),  q_p = (x_i ∘ x_j)·p
// One block per batch element; 256 threads; 5 pairs/thread.
// Inner loop uses Blackwell packed f32x2 FMA (2 FMAs per issue slot).

#define NF 50
#define NE 64
#define NA 10
#define NPAIR 1225
#define THREADS 256
#define PPT 5
#define XPITCH 66           // even (float2-aligned), 33 dwords -> conflict-free LDS.64

typedef unsigned long long u64;

__device__ __forceinline__ u64 f2_mul(u64 a, u64 b) {
    u64 d; asm("mul.rn.f32x2 %0, %1, %2;" : "=l"(d) : "l"(a), "l"(b)); return d;
}
__device__ __forceinline__ u64 f2_fma(u64 a, u64 b, u64 c) {
    u64 d; asm("fma.rn.f32x2 %0, %1, %2, %3;" : "=l"(d) : "l"(a), "l"(b), "l"(c)); return d;
}
__device__ __forceinline__ u64 f2_pack(float lo, float hi) {
    u64 d; asm("mov.b64 %0, {%1, %2};" : "=l"(d) : "f"(lo), "f"(hi)); return d;
}
__device__ __forceinline__ void f2_unpack(u64 v, float& lo, float& hi) {
    asm("mov.b64 {%0, %1}, %2;" : "=f"(lo), "=f"(hi) : "l"(v));
}

__global__ __launch_bounds__(THREADS, 2)
void afm_kernel(const float* __restrict__ x,
                const float* __restrict__ W,
                const float* __restrict__ bvec,
                const float* __restrict__ hvec,
                const float* __restrict__ pvec,
                float* __restrict__ out)
{
    __shared__ float xs[NF * XPITCH];
    __shared__ float Ws[NE * NA];
    __shared__ float ps[NE];
    __shared__ float bs[NA];
    __shared__ float hs[NA];
    __shared__ unsigned char pairI[NPAIR];
    __shared__ unsigned char pairJ[NPAIR];
    __shared__ float red[32];
    __shared__ float red2[32];
    __shared__ float bcast;

    const int tid  = threadIdx.x;
    const int lane = tid & 31;
    const int wid  = tid >> 5;
    const int b    = blockIdx.x;

    // ---- load x[b] into padded smem ----
    const float* xb = x + (size_t)b * (NF * NE);
    for (int idx = tid; idx < NF * NE; idx += THREADS) {
        int r = idx >> 6;
        int c = idx & 63;
        xs[r * XPITCH + c] = xb[idx];
    }
    for (int idx = tid; idx < NE * NA; idx += THREADS) Ws[idx] = W[idx];
    for (int idx = tid; idx < NE; idx += THREADS)      ps[idx] = pvec[idx];
    if (tid < NA) { bs[tid] = bvec[tid]; hs[tid] = hvec[tid]; }

    // ---- pair LUT: triu_indices(F, k=1), i-major ----
    for (int p = tid; p < NPAIR; p += THREADS) {
        float fp = (float)p;
        int i = (int)((2.0f * NF - 1.0f -
                       sqrtf((2.0f * NF - 1.0f) * (2.0f * NF - 1.0f) - 8.0f * fp)) * 0.5f);
        if (i < 0) i = 0;
        if (i > NF - 2) i = NF - 2;
        while (i + 1 <= NF - 2 && (i + 1) * (2 * NF - 1 - (i + 1)) / 2 <= p) ++i;
        while (i > 0 && i * (2 * NF - 1 - i) / 2 > p) --i;
        int j = p - i * (2 * NF - 1 - i) / 2 + i + 1;
        pairI[p] = (unsigned char)i;
        pairJ[p] = (unsigned char)j;
    }
    __syncthreads();

    int xioff[PPT], xjoff[PPT];
    bool valid[PPT];
#pragma unroll
    for (int k = 0; k < PPT; ++k) {
        int p = tid + k * THREADS;
        if (p < NPAIR) {
            xioff[k] = (int)pairI[p] * XPITCH;
            xjoff[k] = (int)pairJ[p] * XPITCH;
            valid[k] = true;
        } else {
            xioff[k] = 0;
            xjoff[k] = XPITCH;
            valid[k] = false;
        }
    }

    // ---- phase 1: packed accumulators ----
    // acc2[t][k] lanes = (f=2k, f=2k+1), full sums over e.
    // accq2[t]  lanes  = (even-e partial, odd-e partial) of q.
    u64 acc2[PPT][NA / 2];
    u64 accq2[PPT];
#pragma unroll
    for (int t = 0; t < PPT; ++t) {
        accq2[t] = 0ull;
#pragma unroll
        for (int k = 0; k < NA / 2; ++k) acc2[t][k] = 0ull;
    }

#pragma unroll 1
    for (int ec = 0; ec < NE; ec += 2) {
        // packed weights for e0=ec, e1=ec+1 (broadcast LDS.64)
        u64 w0p[NA / 2], w1p[NA / 2];
#pragma unroll
        for (int k = 0; k < NA / 2; ++k) {
            w0p[k] = *reinterpret_cast<const u64*>(Ws + ec * NA + 2 * k);
            w1p[k] = *reinterpret_cast<const u64*>(Ws + (ec + 1) * NA + 2 * k);
        }
        u64 pp2 = *reinterpret_cast<const u64*>(ps + ec);

#pragma unroll
        for (int t = 0; t < PPT; ++t) {
            u64 xi2 = *reinterpret_cast<const u64*>(xs + xioff[t] + ec);
            u64 xj2 = *reinterpret_cast<const u64*>(xs + xjoff[t] + ec);
            u64 pr2 = f2_mul(xi2, xj2);                 // (pr0, pr1)
            accq2[t] = f2_fma(pr2, pp2, accq2[t]);      // q even/odd partials
            float pr0, pr1;
            f2_unpack(pr2, pr0, pr1);
            u64 prA = f2_pack(pr0, pr0);
            u64 prB = f2_pack(pr1, pr1);
#pragma unroll
            for (int k = 0; k < NA / 2; ++k)
                acc2[t][k] = f2_fma(prA, w0p[k], acc2[t][k]);
#pragma unroll
            for (int k = 0; k < NA / 2; ++k)
                acc2[t][k] = f2_fma(prB, w1p[k], acc2[t][k]);
        }
    }

    // ---- logits + q scalars ----
    float logit[PPT], qv[PPT];
#pragma unroll
    for (int t = 0; t < PPT; ++t) {
        float l = 0.0f;
#pragma unroll
        for (int k = 0; k < NA / 2; ++k) {
            float a0, a1;
            f2_unpack(acc2[t][k], a0, a1);
            a0 += bs[2 * k];
            a1 += bs[2 * k + 1];
            a0 = a0 > 0.0f ? a0 : 0.0f;
            a1 = a1 > 0.0f ? a1 : 0.0f;
            l = fmaf(hs[2 * k], a0, l);
            l = fmaf(hs[2 * k + 1], a1, l);
        }
        float q0, q1;
        f2_unpack(accq2[t], q0, q1);
        qv[t] = q0 + q1;
        logit[t] = valid[t] ? l : -INFINITY;
    }

    // ---- phase 2: softmax-weighted scalar reduction ----
    float m = logit[0];
#pragma unroll
    for (int t = 1; t < PPT; ++t) m = fmaxf(m, logit[t]);
#pragma unroll
    for (int o = 16; o > 0; o >>= 1)
        m = fmaxf(m, __shfl_xor_sync(0xFFFFFFFFu, m, o));
    if (lane == 0) red[wid] = m;
    __syncthreads();
    if (tid == 0) {
        float mm = red[0];
#pragma unroll
        for (int w = 1; w < THREADS / 32; ++w) mm = fmaxf(mm, red[w]);
        bcast = mm;
    }
    __syncthreads();
    const float mAll = bcast;

    float s = 0.0f, sq = 0.0f;
#pragma unroll
    for (int t = 0; t < PPT; ++t) {
        if (valid[t]) {
            float e = expf(logit[t] - mAll);
            s += e;
            sq = fmaf(e, qv[t], sq);
        }
    }
#pragma unroll
    for (int o = 16; o > 0; o >>= 1) {
        s  += __shfl_xor_sync(0xFFFFFFFFu, s, o);
        sq += __shfl_xor_sync(0xFFFFFFFFu, sq, o);
    }
    if (lane == 0) { red[wid] = s; red2[wid] = sq; }
    __syncthreads();
    if (tid == 0) {
        float ss = 0.0f, ssq = 0.0f;
#pragma unroll
        for (int w = 0; w < THREADS / 32; ++w) { ss += red[w]; ssq += red2[w]; }
        out[b] = ssq / ss;
    }
}

extern "C" void kernel_launch(void* const* d_in, const int* in_sizes, int n_in,
                              void* d_out, int out_size)
{
    const float* x = (const float*)d_in[0];   // [B, 50, 64]
    const float* W = (const float*)d_in[1];   // [64, 10]
    const float* b = (const float*)d_in[2];   // [10]
    const float* h = (const float*)d_in[3];   // [10, 1]
    const float* p = (const float*)d_in[4];   // [64, 1]
    float* out = (float*)d_out;               // [B, 1]

    int B = in_sizes[0] / (NF * NE);
    afm_kernel<<<B, THREADS>>>(x, W, b, h, p, out);
}

// round 3
// speedup vs baseline: 1.1982x; 1.0712x over previous
#include <cuda_runtime.h>
#include <math.h>

// AFM layer: B=2048, F=50, E=64, A=10, P=1225.
// out[b] = sum_p softmax(l)_p * q_p
//   l_p = sum_f h_f * relu( (x_i ∘ x_j)·W_f + b_f ),  q_p = (x_i ∘ x_j)·p
// One block per batch element; 256 threads; 5 pairs/thread.
// f32x2 packed FMA; all shared traffic as 128-bit loads; q folded into W col 10.

#define NF 50
#define NE 64
#define NA 10
#define WC 12               // padded weight cols: 0-9 = W, 10 = p, 11 = 0
#define NPAIR 1225
#define THREADS 256
#define PPT 5
#define XPITCH 68           // 16B-aligned rows; stride 68 words -> conflict-free LDS.128

typedef unsigned long long u64;

__device__ __forceinline__ u64 f2_mul(u64 a, u64 b) {
    u64 d; asm("mul.rn.f32x2 %0, %1, %2;" : "=l"(d) : "l"(a), "l"(b)); return d;
}
__device__ __forceinline__ u64 f2_fma(u64 a, u64 b, u64 c) {
    u64 d; asm("fma.rn.f32x2 %0, %1, %2, %3;" : "=l"(d) : "l"(a), "l"(b), "l"(c)); return d;
}
__device__ __forceinline__ u64 f2_pack(float lo, float hi) {
    u64 d; asm("mov.b64 %0, {%1, %2};" : "=l"(d) : "f"(lo), "f"(hi)); return d;
}
__device__ __forceinline__ void f2_unpack(u64 v, float& lo, float& hi) {
    asm("mov.b64 {%0, %1}, %2;" : "=f"(lo), "=f"(hi) : "l"(v));
}

__global__ __launch_bounds__(THREADS, 2)
void afm_kernel(const float* __restrict__ x,
                const float* __restrict__ W,
                const float* __restrict__ bvec,
                const float* __restrict__ hvec,
                const float* __restrict__ pvec,
                float* __restrict__ out)
{
    __shared__ __align__(16) float xs[NF * XPITCH];   // 13600 B
    __shared__ __align__(16) float Ws[NE * WC];       // 3072 B
    __shared__ float bs[NA];
    __shared__ float hs[NA];
    __shared__ unsigned char pairI[NPAIR];
    __shared__ unsigned char pairJ[NPAIR];
    __shared__ float red[32];
    __shared__ float red2[32];
    __shared__ float bcast;

    const int tid  = threadIdx.x;
    const int lane = tid & 31;
    const int wid  = tid >> 5;
    const int b    = blockIdx.x;

    // ---- load x[b] into padded smem ----
    const float* xb = x + (size_t)b * (NF * NE);
    for (int idx = tid; idx < NF * NE; idx += THREADS) {
        int r = idx >> 6;
        int c = idx & 63;
        xs[r * XPITCH + c] = xb[idx];
    }
    // ---- padded weights: cols 0-9 = W row, col 10 = p, col 11 = 0 ----
    for (int idx = tid; idx < NE * WC; idx += THREADS) {
        int e = idx / WC;
        int c = idx - e * WC;
        float v;
        if (c < NA)        v = W[e * NA + c];
        else if (c == NA)  v = pvec[e];
        else               v = 0.0f;
        Ws[idx] = v;
    }
    if (tid < NA) { bs[tid] = bvec[tid]; hs[tid] = hvec[tid]; }

    // ---- pair LUT: triu_indices(F, k=1), i-major ----
    for (int p = tid; p < NPAIR; p += THREADS) {
        float fp = (float)p;
        int i = (int)((2.0f * NF - 1.0f -
                       sqrtf((2.0f * NF - 1.0f) * (2.0f * NF - 1.0f) - 8.0f * fp)) * 0.5f);
        if (i < 0) i = 0;
        if (i > NF - 2) i = NF - 2;
        while (i + 1 <= NF - 2 && (i + 1) * (2 * NF - 1 - (i + 1)) / 2 <= p) ++i;
        while (i > 0 && i * (2 * NF - 1 - i) / 2 > p) --i;
        int j = p - i * (2 * NF - 1 - i) / 2 + i + 1;
        pairI[p] = (unsigned char)i;
        pairJ[p] = (unsigned char)j;
    }
    __syncthreads();

    int xioff[PPT], xjoff[PPT];
    bool valid[PPT];
#pragma unroll
    for (int k = 0; k < PPT; ++k) {
        int p = tid + k * THREADS;
        if (p < NPAIR) {
            xioff[k] = (int)pairI[p] * XPITCH;
            xjoff[k] = (int)pairJ[p] * XPITCH;
            valid[k] = true;
        } else {
            xioff[k] = 0;
            xjoff[k] = XPITCH;
            valid[k] = false;
        }
    }

    // ---- phase 1: packed accumulators ----
    // acc2[t][k] lanes = (col 2k, col 2k+1); k=5 lane0 carries q, lane1 stays 0.
    u64 acc2[PPT][WC / 2];
#pragma unroll
    for (int t = 0; t < PPT; ++t)
#pragma unroll
        for (int k = 0; k < WC / 2; ++k) acc2[t][k] = 0ull;

#pragma unroll 1
    for (int ec = 0; ec < NE; ec += 4) {
        // weights for 4 e-rows, each as 3 LDS.128 -> 6 packed u64 (broadcast)
        u64 wp[4][WC / 2];
#pragma unroll
        for (int e = 0; e < 4; ++e) {
            const ulonglong2* wr = reinterpret_cast<const ulonglong2*>(Ws + (ec + e) * WC);
            ulonglong2 a = wr[0], bq = wr[1], c = wr[2];
            wp[e][0] = a.x;  wp[e][1] = a.y;
            wp[e][2] = bq.x; wp[e][3] = bq.y;
            wp[e][4] = c.x;  wp[e][5] = c.y;
        }
#pragma unroll
        for (int t = 0; t < PPT; ++t) {
            ulonglong2 xi = *reinterpret_cast<const ulonglong2*>(xs + xioff[t] + ec);
            ulonglong2 xj = *reinterpret_cast<const ulonglong2*>(xs + xjoff[t] + ec);
            u64 pr01 = f2_mul(xi.x, xj.x);
            u64 pr23 = f2_mul(xi.y, xj.y);
            float p0, p1, p2, p3;
            f2_unpack(pr01, p0, p1);
            f2_unpack(pr23, p2, p3);
            u64 br0 = f2_pack(p0, p0);
            u64 br1 = f2_pack(p1, p1);
            u64 br2 = f2_pack(p2, p2);
            u64 br3 = f2_pack(p3, p3);
#pragma unroll
            for (int k = 0; k < WC / 2; ++k) acc2[t][k] = f2_fma(br0, wp[0][k], acc2[t][k]);
#pragma unroll
            for (int k = 0; k < WC / 2; ++k) acc2[t][k] = f2_fma(br1, wp[1][k], acc2[t][k]);
#pragma unroll
            for (int k = 0; k < WC / 2; ++k) acc2[t][k] = f2_fma(br2, wp[2][k], acc2[t][k]);
#pragma unroll
            for (int k = 0; k < WC / 2; ++k) acc2[t][k] = f2_fma(br3, wp[3][k], acc2[t][k]);
        }
    }

    // ---- logits + q scalars ----
    float logit[PPT], qv[PPT];
#pragma unroll
    for (int t = 0; t < PPT; ++t) {
        float l = 0.0f;
#pragma unroll
        for (int k = 0; k < NA / 2; ++k) {
            float a0, a1;
            f2_unpack(acc2[t][k], a0, a1);
            a0 += bs[2 * k];
            a1 += bs[2 * k + 1];
            a0 = a0 > 0.0f ? a0 : 0.0f;
            a1 = a1 > 0.0f ? a1 : 0.0f;
            l = fmaf(hs[2 * k], a0, l);
            l = fmaf(hs[2 * k + 1], a1, l);
        }
        float q0, q1;
        f2_unpack(acc2[t][5], q0, q1);
        qv[t] = q0;                         // lane1 accumulated zeros
        logit[t] = valid[t] ? l : -INFINITY;
    }

    // ---- phase 2: softmax-weighted scalar reduction ----
    float m = logit[0];
#pragma unroll
    for (int t = 1; t < PPT; ++t) m = fmaxf(m, logit[t]);
#pragma unroll
    for (int o = 16; o > 0; o >>= 1)
        m = fmaxf(m, __shfl_xor_sync(0xFFFFFFFFu, m, o));
    if (lane == 0) red[wid] = m;
    __syncthreads();
    if (tid == 0) {
        float mm = red[0];
#pragma unroll
        for (int w = 1; w < THREADS / 32; ++w) mm = fmaxf(mm, red[w]);
        bcast = mm;
    }
    __syncthreads();
    const float mAll = bcast;

    float s = 0.0f, sq = 0.0f;
#pragma unroll
    for (int t = 0; t < PPT; ++t) {
        if (valid[t]) {
            float e = expf(logit[t] - mAll);
            s += e;
            sq = fmaf(e, qv[t], sq);
        }
    }
#pragma unroll
    for (int o = 16; o > 0; o >>= 1) {
        s  += __shfl_xor_sync(0xFFFFFFFFu, s, o);
        sq += __shfl_xor_sync(0xFFFFFFFFu, sq, o);
    }
    if (lane == 0) { red[wid] = s; red2[wid] = sq; }
    __syncthreads();
    if (tid == 0) {
        float ss = 0.0f, ssq = 0.0f;
#pragma unroll
        for (int w = 0; w < THREADS / 32; ++w) { ss += red[w]; ssq += red2[w]; }
        out[b] = ssq / ss;
    }
}

extern "C" void kernel_launch(void* const* d_in, const int* in_sizes, int n_in,
                              void* d_out, int out_size)
{
    const float* x = (const float*)d_in[0];   // [B, 50, 64]
    const float* W = (const float*)d_in[1];   // [64, 10]
    const float* b = (const float*)d_in[2];   // [10]
    const float* h = (const float*)d_in[3];   // [10, 1]
    const float* p = (const float*)d_in[4];   // [64, 1]
    float* out = (float*)d_out;               // [B, 1]

    int B = in_sizes[0] / (NF * NE);
    afm_kernel<<<B, THREADS>>>(x, W, b, h, p, out);
}